// round 16
// baseline (speedup 1.0000x reference)
#include <cuda_runtime.h>
#include <cuda_bf16.h>
#include <cstdint>

#define N_NODES_MAX 50000
#define N_EDGES_MAX 800000
#define D_IN_C      128
#define H1_C        128
#define H2_C        64
#define H3_C        64
#define NPROTO_C    16
#define MLP_H_C     8

// ---------------- scratch (static __device__, allocation-free) ----------------
__device__ int    g_cnt   [N_NODES_MAX];
__device__ int    g_rowptr[N_NODES_MAX + 1];
__device__ int    g_cursor[N_NODES_MAX];
__device__ int    g_col   [N_EDGES_MAX];
__device__ float  g_dinv  [N_NODES_MAX];
__device__ __align__(16) float g_S[(size_t)N_NODES_MAX * 128];
__device__ __align__(16) float g_H[(size_t)N_NODES_MAX * 128];
__device__ int    g_is64;

// ---------------- index dtype detection ----------------
__global__ void detect_idx_kernel(const void* ei, int n) {
    const long long* p = (const long long*)ei;
    bool ok = true;
    #pragma unroll
    for (int i = 0; i < 4; i++) {
        long long v = p[i];
        if (v < 0 || v >= (long long)n) ok = false;
    }
    g_is64 = ok ? 1 : 0;
}

// ---------------- CSR build (4 edges / thread, vectorized) ----------------
__global__ void count_kernel(const void* ei, int ne) {
    int base = (blockIdx.x * blockDim.x + threadIdx.x) * 4;
    if (base >= ne) return;
    bool vec = (base + 3 < ne) && ((ne & 3) == 0);
    if (g_is64) {
        const long long* p = (const long long*)ei + ne;  // dst array
        if (vec) {
            longlong2 d0 = __ldg((const longlong2*)(p + base));
            longlong2 d1 = __ldg((const longlong2*)(p + base + 2));
            atomicAdd(&g_cnt[(int)d0.x], 1);
            atomicAdd(&g_cnt[(int)d0.y], 1);
            atomicAdd(&g_cnt[(int)d1.x], 1);
            atomicAdd(&g_cnt[(int)d1.y], 1);
        } else {
            for (int j = 0; j < 4 && base + j < ne; j++)
                atomicAdd(&g_cnt[(int)p[base + j]], 1);
        }
    } else {
        const int* p = (const int*)ei + ne;
        if (vec) {
            int4 d = __ldg((const int4*)(p + base));
            atomicAdd(&g_cnt[d.x], 1);
            atomicAdd(&g_cnt[d.y], 1);
            atomicAdd(&g_cnt[d.z], 1);
            atomicAdd(&g_cnt[d.w], 1);
        } else {
            for (int j = 0; j < 4 && base + j < ne; j++)
                atomicAdd(&g_cnt[p[base + j]], 1);
        }
    }
}

// single-block exclusive scan over g_cnt -> rowptr/cursor, plus dinv
__global__ void scan_kernel(int n) {
    __shared__ int sh[1024];
    const int t = threadIdx.x;
    const int CH = (n + 1023) / 1024;
    const int base = t * CH;

    int s = 0;
    for (int j = 0; j < CH; j++) {
        int i = base + j;
        if (i < n) s += g_cnt[i];
    }
    sh[t] = s;
    __syncthreads();
    for (int d = 1; d < 1024; d <<= 1) {
        int v = (t >= d) ? sh[t - d] : 0;
        __syncthreads();
        sh[t] += v;
        __syncthreads();
    }
    int running = sh[t] - s;
    for (int j = 0; j < CH; j++) {
        int i = base + j;
        if (i < n) {
            int c = g_cnt[i];
            g_rowptr[i] = running;
            g_cursor[i] = running;
            g_dinv[i]   = rsqrtf((float)(c + 1));
            running += c;
        }
    }
    if (t == 1023) g_rowptr[n] = sh[1023];
}

__global__ void fill_kernel(const void* ei, int ne) {
    int base = (blockIdx.x * blockDim.x + threadIdx.x) * 4;
    if (base >= ne) return;
    bool vec = (base + 3 < ne) && ((ne & 3) == 0);
    int src[4], dst[4], cnt4 = 4;
    if (g_is64) {
        const long long* ps = (const long long*)ei;
        const long long* pd = ps + ne;
        if (vec) {
            longlong2 s0 = __ldg((const longlong2*)(ps + base));
            longlong2 s1 = __ldg((const longlong2*)(ps + base + 2));
            longlong2 d0 = __ldg((const longlong2*)(pd + base));
            longlong2 d1 = __ldg((const longlong2*)(pd + base + 2));
            src[0]=(int)s0.x; src[1]=(int)s0.y; src[2]=(int)s1.x; src[3]=(int)s1.y;
            dst[0]=(int)d0.x; dst[1]=(int)d0.y; dst[2]=(int)d1.x; dst[3]=(int)d1.y;
        } else {
            cnt4 = 0;
            for (int j = 0; j < 4 && base + j < ne; j++) {
                src[cnt4] = (int)ps[base + j]; dst[cnt4] = (int)pd[base + j]; cnt4++;
            }
        }
    } else {
        const int* ps = (const int*)ei;
        const int* pd = ps + ne;
        if (vec) {
            int4 s = __ldg((const int4*)(ps + base));
            int4 d = __ldg((const int4*)(pd + base));
            src[0]=s.x; src[1]=s.y; src[2]=s.z; src[3]=s.w;
            dst[0]=d.x; dst[1]=d.y; dst[2]=d.z; dst[3]=d.w;
        } else {
            cnt4 = 0;
            for (int j = 0; j < 4 && base + j < ne; j++) {
                src[cnt4] = ps[base + j]; dst[cnt4] = pd[base + j]; cnt4++;
            }
        }
    }
    int pos[4];
    #pragma unroll
    for (int j = 0; j < 4; j++)
        if (j < cnt4) pos[j] = atomicAdd(&g_cursor[dst[j]], 1);
    #pragma unroll
    for (int j = 0; j < 4; j++)
        if (j < cnt4) g_col[pos[j]] = src[j];
}

// ---------------- GEMM (+optional row-scale):  S = (Hin @ W) [* dinv[row]] ----------------
// Register-blocked 8x8, packed fp32x2 FMA. hs stored as pre-duplicated (a,a)
// float2 pairs -> LDS.64 yields the packed multiplier directly (no movs).
// ws uses the conflict-free split-half layout. W is [KDIM, NDIM] row-major.
template<int KDIM, int NDIM, int BM, int KC, int NTHREADS, bool SCALE>
__global__ void __launch_bounds__(NTHREADS, 5)
gemm_scale_kernel(const float* __restrict__ Hin,
                  const float* __restrict__ W,
                  float* __restrict__ S,
                  int n) {
    constexpr int TM = 8, TN = 8;
    constexpr int TCOLS = NDIM / TN;
    constexpr int TROWS = NTHREADS / TCOLS;
    static_assert(TROWS * TM == BM, "tile shape");
    constexpr int HSP = KC + 1;   // float2 row stride 264B: odd multiple of 8 -> tr rows on distinct banks

    __shared__ float ws[KC][NDIM];
    __shared__ float2 hs2[BM][HSP];

    const int tc = threadIdx.x % TCOLS;
    const int tr = threadIdx.x / TCOLS;
    const int row0 = blockIdx.x * BM;

    unsigned long long acc[TM][4];
    #pragma unroll
    for (int m = 0; m < TM; m++)
        #pragma unroll
        for (int p = 0; p < 4; p++)
            acc[m][p] = 0ULL;  // packed (0.0f, 0.0f)

    for (int kc = 0; kc < KDIM; kc += KC) {
        for (int i = threadIdx.x; i < KC * (NDIM / 4); i += NTHREADS) {
            int kk = i / (NDIM / 4), c4 = i % (NDIM / 4);
            float4 v = ((const float4*)(W + (size_t)(kc + kk) * NDIM))[c4];
            int phys = ((c4 & 1) ? (NDIM / 8) : 0) + (c4 >> 1);  // split-half permute
            ((float4*)ws[kk])[phys] = v;
        }
        for (int i = threadIdx.x; i < BM * (KC / 4); i += NTHREADS) {
            int rr = i / (KC / 4), c4 = i % (KC / 4);
            int grow = row0 + rr;
            float4 v = make_float4(0.f, 0.f, 0.f, 0.f);
            if (grow < n)
                v = ((const float4*)(Hin + (size_t)grow * KDIM + kc))[c4];
            float2* d = &hs2[rr][c4 * 4];
            d[0] = make_float2(v.x, v.x);
            d[1] = make_float2(v.y, v.y);
            d[2] = make_float2(v.z, v.z);
            d[3] = make_float2(v.w, v.w);
        }
        __syncthreads();

        #pragma unroll 4
        for (int k = 0; k < KC; k++) {
            ulonglong2 w01 = *(const ulonglong2*)&ws[k][tc * 4];
            ulonglong2 w23 = *(const ulonglong2*)&ws[k][NDIM / 2 + tc * 4];
            unsigned long long ad[TM];
            #pragma unroll
            for (int m = 0; m < TM; m++)
                ad[m] = *(const unsigned long long*)&hs2[tr * TM + m][k];  // (a,a) via LDS.64
            #pragma unroll
            for (int m = 0; m < TM; m++) {
                asm("fma.rn.f32x2 %0, %1, %2, %0;" : "+l"(acc[m][0]) : "l"(ad[m]), "l"(w01.x));
                asm("fma.rn.f32x2 %0, %1, %2, %0;" : "+l"(acc[m][1]) : "l"(ad[m]), "l"(w01.y));
                asm("fma.rn.f32x2 %0, %1, %2, %0;" : "+l"(acc[m][2]) : "l"(ad[m]), "l"(w23.x));
                asm("fma.rn.f32x2 %0, %1, %2, %0;" : "+l"(acc[m][3]) : "l"(ad[m]), "l"(w23.y));
            }
        }
        __syncthreads();
    }

    #pragma unroll
    for (int m = 0; m < TM; m++) {
        int row = row0 + tr * TM + m;
        if (row < n) {
            unsigned long long r0 = acc[m][0], r1 = acc[m][1], r2 = acc[m][2], r3 = acc[m][3];
            if (SCALE) {
                float dv = g_dinv[row];
                unsigned long long dvp;
                asm("mov.b64 %0, {%1, %1};" : "=l"(dvp) : "f"(dv));
                asm("mul.rn.f32x2 %0, %0, %1;" : "+l"(r0) : "l"(dvp));
                asm("mul.rn.f32x2 %0, %0, %1;" : "+l"(r1) : "l"(dvp));
                asm("mul.rn.f32x2 %0, %0, %1;" : "+l"(r2) : "l"(dvp));
                asm("mul.rn.f32x2 %0, %0, %1;" : "+l"(r3) : "l"(dvp));
            }
            ulonglong2 o0; o0.x = r0; o0.y = r1;
            ulonglong2 o1; o1.x = r2; o1.y = r3;
            *(ulonglong2*)(S + (size_t)row * NDIM + tc * TN)     = o0;
            *(ulonglong2*)(S + (size_t)row * NDIM + tc * TN + 4) = o1;
        }
    }
}

// ---------------- row scale: S[row,:] *= dinv[row]  (layer 1 only) ----------------
__global__ void scale_kernel(float* __restrict__ S, int n) {
    long long t = (long long)blockIdx.x * blockDim.x + threadIdx.x;
    if (t >= (long long)n * 32) return;
    int row = (int)(t >> 5);
    int c = (int)(t & 31);
    float dv = g_dinv[row];
    float4* p = (float4*)S + ((size_t)row << 5) + c;
    float4 v = *p;
    v.x *= dv; v.y *= dv; v.z *= dv; v.w *= dv;
    *p = v;
}

// ---------------- CSR aggregation (+self loop +dinv +bias +relu) ----------------
template<int NDIM>
__global__ void agg_kernel(const float* __restrict__ S,
                           const float* __restrict__ b,
                           float* __restrict__ H,
                           int n) {
    constexpr int G = NDIM / 4;
    constexpr int RPW = 32 / G;
    const int warpId = threadIdx.x / 32;
    const int lane = threadIdx.x % 32;
    const int g = lane % G;
    const int row = (blockIdx.x * (blockDim.x / 32) + warpId) * RPW + lane / G;
    if (row >= n) return;

    const float4* S4 = (const float4*)S;
    float4 acc = __ldg(&S4[(size_t)row * G + g]);   // self loop

    const int start = g_rowptr[row];
    const int end   = g_rowptr[row + 1];

    int j = start;
    for (; j + 3 < end; j += 4) {
        int s0 = __ldg(&g_col[j]);
        int s1 = __ldg(&g_col[j + 1]);
        int s2 = __ldg(&g_col[j + 2]);
        int s3 = __ldg(&g_col[j + 3]);
        float4 v0 = __ldg(&S4[(size_t)s0 * G + g]);
        float4 v1 = __ldg(&S4[(size_t)s1 * G + g]);
        float4 v2 = __ldg(&S4[(size_t)s2 * G + g]);
        float4 v3 = __ldg(&S4[(size_t)s3 * G + g]);
        acc.x += (v0.x + v1.x) + (v2.x + v3.x);
        acc.y += (v0.y + v1.y) + (v2.y + v3.y);
        acc.z += (v0.z + v1.z) + (v2.z + v3.z);
        acc.w += (v0.w + v1.w) + (v2.w + v3.w);
    }
    for (; j < end; j++) {
        int s0 = __ldg(&g_col[j]);
        float4 v0 = __ldg(&S4[(size_t)s0 * G + g]);
        acc.x += v0.x; acc.y += v0.y; acc.z += v0.z; acc.w += v0.w;
    }

    float dv = g_dinv[row];
    float4 bb = ((const float4*)b)[g];
    float4 h;
    h.x = fmaxf(dv * acc.x + bb.x, 0.f);
    h.y = fmaxf(dv * acc.y + bb.y, 0.f);
    h.z = fmaxf(dv * acc.z + bb.z, 0.f);
    h.w = fmaxf(dv * acc.w + bb.w, 0.f);
    ((float4*)(H + (size_t)row * NDIM))[g] = h;
}

// ---------------- fused layer-3 aggregation + head ----------------
__global__ void agg_final_kernel(const float* __restrict__ S,
                                 const float* __restrict__ b,
                                 const void* __restrict__ y,
                                 const float* __restrict__ proto,
                                 const float* __restrict__ Wf0,
                                 const float* __restrict__ bf0,
                                 const float* __restrict__ Wf1,
                                 const float* __restrict__ bf1,
                                 float* __restrict__ out,
                                 int n) {
    constexpr int G = 16;
    __shared__ float ps[NPROTO_C][H3_C];
    __shared__ float psq[NPROTO_C];
    __shared__ float w0[NPROTO_C][MLP_H_C];
    __shared__ float b0[MLP_H_C];
    __shared__ float w1[MLP_H_C];
    __shared__ float b1s;

    for (int i = threadIdx.x; i < NPROTO_C * H3_C; i += blockDim.x)
        ps[i / H3_C][i % H3_C] = proto[i];
    for (int i = threadIdx.x; i < NPROTO_C * MLP_H_C; i += blockDim.x)
        w0[i / MLP_H_C][i % MLP_H_C] = Wf0[i];
    if (threadIdx.x < MLP_H_C) {
        b0[threadIdx.x] = bf0[threadIdx.x];
        w1[threadIdx.x] = Wf1[threadIdx.x];
    }
    if (threadIdx.x == 0) b1s = bf1[0];
    __syncthreads();
    if (threadIdx.x < NPROTO_C) {
        float s = 0.f;
        for (int j = 0; j < H3_C; j++) s += ps[threadIdx.x][j] * ps[threadIdx.x][j];
        psq[threadIdx.x] = s;
    }
    __syncthreads();

    const int warpId = threadIdx.x / 32;
    const int lane = threadIdx.x % 32;
    const int g = lane % G;
    int row = (blockIdx.x * (blockDim.x / 32) + warpId) * 2 + lane / G;
    const bool valid = (row < n);
    if (!valid) row = n - 1;   // clamp: keep full warp for shfl

    const float4* S4 = (const float4*)S;
    float4 acc = __ldg(&S4[(size_t)row * G + g]);
    const int start = g_rowptr[row];
    const int end   = g_rowptr[row + 1];
    int j = start;
    for (; j + 3 < end; j += 4) {
        int s0 = __ldg(&g_col[j]);
        int s1 = __ldg(&g_col[j + 1]);
        int s2 = __ldg(&g_col[j + 2]);
        int s3 = __ldg(&g_col[j + 3]);
        float4 v0 = __ldg(&S4[(size_t)s0 * G + g]);
        float4 v1 = __ldg(&S4[(size_t)s1 * G + g]);
        float4 v2 = __ldg(&S4[(size_t)s2 * G + g]);
        float4 v3 = __ldg(&S4[(size_t)s3 * G + g]);
        acc.x += (v0.x + v1.x) + (v2.x + v3.x);
        acc.y += (v0.y + v1.y) + (v2.y + v3.y);
        acc.z += (v0.z + v1.z) + (v2.z + v3.z);
        acc.w += (v0.w + v1.w) + (v2.w + v3.w);
    }
    for (; j < end; j++) {
        int s0 = __ldg(&g_col[j]);
        float4 v0 = __ldg(&S4[(size_t)s0 * G + g]);
        acc.x += v0.x; acc.y += v0.y; acc.z += v0.z; acc.w += v0.w;
    }

    float dv = g_dinv[row];
    float4 bb = ((const float4*)b)[g];
    float4 h;
    h.x = fmaxf(dv * acc.x + bb.x, 0.f);
    h.y = fmaxf(dv * acc.y + bb.y, 0.f);
    h.z = fmaxf(dv * acc.z + bb.z, 0.f);
    h.w = fmaxf(dv * acc.w + bb.w, 0.f);

    float hh = h.x * h.x + h.y * h.y + h.z * h.z + h.w * h.w;
    float dot[NPROTO_C];
    #pragma unroll
    for (int p = 0; p < NPROTO_C; p++) {
        dot[p] = h.x * ps[p][4 * g + 0] + h.y * ps[p][4 * g + 1]
               + h.z * ps[p][4 * g + 2] + h.w * ps[p][4 * g + 3];
    }

    #pragma unroll
    for (int off = 8; off >= 1; off >>= 1) {
        hh += __shfl_xor_sync(0xffffffffu, hh, off);
        #pragma unroll
        for (int p = 0; p < NPROTO_C; p++)
            dot[p] += __shfl_xor_sync(0xffffffffu, dot[p], off);
    }

    float d2 = fmaxf(hh + psq[g] - 2.f * dot[g], 0.f);
    float sim = logf((d2 + 1.0f) / (d2 + 1e-4f));
    float z[MLP_H_C];
    #pragma unroll
    for (int jj = 0; jj < MLP_H_C; jj++) z[jj] = sim * w0[g][jj];
    #pragma unroll
    for (int off = 8; off >= 1; off >>= 1) {
        #pragma unroll
        for (int jj = 0; jj < MLP_H_C; jj++)
            z[jj] += __shfl_xor_sync(0xffffffffu, z[jj], off);
    }

    if (g == 0 && valid) {
        float t = b1s;
        #pragma unroll
        for (int jj = 0; jj < MLP_H_C; jj++) {
            float x = z[jj] + b0[jj];
            float gl = 0.5f * x * (1.0f + erff(x * 0.70710678118654752f));
            t += gl * w1[jj];
        }
        out[row] = 1.0f / (1.0f + expf(-t));
        if (g_is64) out[n + row] = (float)((const long long*)y)[row];
        else        out[n + row] = (float)((const int*)y)[row];
    }
}

// ---------------- launch ----------------
extern "C" void kernel_launch(void* const* d_in, const int* in_sizes, int n_in,
                              void* d_out, int out_size) {
    const float* x     = (const float*)d_in[0];
    const void*  ei    = d_in[1];
    const void*  y     = d_in[2];
    const float* W1    = (const float*)d_in[3];
    const float* b1    = (const float*)d_in[4];
    const float* W2    = (const float*)d_in[5];
    const float* b2    = (const float*)d_in[6];
    const float* W3    = (const float*)d_in[7];
    const float* b3    = (const float*)d_in[8];
    const float* proto = (const float*)d_in[9];
    const float* Wf0   = (const float*)d_in[10];
    const float* bf0   = (const float*)d_in[11];
    const float* Wf1   = (const float*)d_in[12];
    const float* bf1   = (const float*)d_in[13];
    float* out = (float*)d_out;

    const int n  = in_sizes[0] / D_IN_C;
    const int ne = in_sizes[1] / 2;

    float* S = nullptr; float* H = nullptr; int* cnt = nullptr;
    cudaGetSymbolAddress((void**)&S, g_S);
    cudaGetSymbolAddress((void**)&H, g_H);
    cudaGetSymbolAddress((void**)&cnt, g_cnt);

    // streams/events created once, on the (uncaptured) correctness call
    static cudaStream_t s_side = nullptr;
    static cudaEvent_t ev_fork = nullptr, ev_join = nullptr;
    if (s_side == nullptr) {
        cudaStreamCreateWithFlags(&s_side, cudaStreamNonBlocking);
        cudaEventCreateWithFlags(&ev_fork, cudaEventDisableTiming);
        cudaEventCreateWithFlags(&ev_join, cudaEventDisableTiming);
    }

    // ---- fork: CSR build on side stream, gemm1 (no dinv) on main ----
    cudaEventRecord(ev_fork, 0);
    cudaStreamWaitEvent(s_side, ev_fork, 0);

    int nt4 = (ne + 3) / 4;
    cudaMemsetAsync(cnt, 0, (size_t)n * sizeof(int), s_side);
    detect_idx_kernel<<<1, 1, 0, s_side>>>(ei, n);
    count_kernel<<<(nt4 + 255) / 256, 256, 0, s_side>>>(ei, ne);
    scan_kernel<<<1, 1024, 0, s_side>>>(n);
    fill_kernel<<<(nt4 + 255) / 256, 256, 0, s_side>>>(ei, ne);
    cudaEventRecord(ev_join, s_side);

    // gemm1: 128 -> 128, BM=64, 128 threads, no row scale (dinv not ready yet)
    gemm_scale_kernel<D_IN_C, H1_C, 64, 32, 128, false>
        <<<(n + 63) / 64, 128>>>(x, W1, S, n);

    // ---- join, then apply dinv to S ----
    cudaStreamWaitEvent(0, ev_join, 0);
    {
        long long tot = (long long)n * 32;
        scale_kernel<<<(unsigned)((tot + 255) / 256), 256>>>(S, n);
    }

    // ---- layer 1 aggregation ----
    {
        int rpb = (256 / 32) * (32 / (H1_C / 4));
        agg_kernel<H1_C><<<(n + rpb - 1) / rpb, 256>>>(S, b1, H, n);
    }
    // ---- layer 2: 128 -> 64 ----
    {
        gemm_scale_kernel<H1_C, H2_C, 128, 32, 128, true>
            <<<(n + 127) / 128, 128>>>(H, W2, S, n);
        int rpb = (256 / 32) * (32 / (H2_C / 4));
        agg_kernel<H2_C><<<(n + rpb - 1) / rpb, 256>>>(S, b2, H, n);
    }
    // ---- layer 3: 64 -> 64, fused with head ----
    {
        gemm_scale_kernel<H2_C, H3_C, 128, 32, 128, true>
            <<<(n + 127) / 128, 128>>>(H, W3, S, n);
        int rpb = (256 / 32) * 2;   // 16 rows per 256-thread block
        agg_final_kernel<<<(n + rpb - 1) / rpb, 256>>>(S, b3, y, proto,
                                                       Wf0, bf0, Wf1, bf1, out, n);
    }
}

// round 17
// speedup vs baseline: 1.1569x; 1.1569x over previous
#include <cuda_runtime.h>
#include <cuda_bf16.h>
#include <cstdint>

#define N_NODES_MAX 50000
#define N_EDGES_MAX 800000
#define D_IN_C      128
#define H1_C        128
#define H2_C        64
#define H3_C        64
#define NPROTO_C    16
#define MLP_H_C     8

// ---------------- scratch (static __device__, allocation-free) ----------------
__device__ int    g_cnt   [N_NODES_MAX];
__device__ int    g_rowptr[N_NODES_MAX + 1];
__device__ int    g_cursor[N_NODES_MAX];
__device__ int    g_col   [N_EDGES_MAX];
__device__ float  g_dinv  [N_NODES_MAX];
__device__ __align__(16) float g_S[(size_t)N_NODES_MAX * 128];
__device__ __align__(16) float g_H[(size_t)N_NODES_MAX * 128];
__device__ int    g_is64;

// ---------------- index dtype detection ----------------
__global__ void detect_idx_kernel(const void* ei, int n) {
    const long long* p = (const long long*)ei;
    bool ok = true;
    #pragma unroll
    for (int i = 0; i < 4; i++) {
        long long v = p[i];
        if (v < 0 || v >= (long long)n) ok = false;
    }
    g_is64 = ok ? 1 : 0;
}

// ---------------- CSR build (4 edges / thread, vectorized) ----------------
__global__ void count_kernel(const void* ei, int ne) {
    int base = (blockIdx.x * blockDim.x + threadIdx.x) * 4;
    if (base >= ne) return;
    bool vec = (base + 3 < ne) && ((ne & 3) == 0);
    if (g_is64) {
        const long long* p = (const long long*)ei + ne;  // dst array
        if (vec) {
            longlong2 d0 = __ldg((const longlong2*)(p + base));
            longlong2 d1 = __ldg((const longlong2*)(p + base + 2));
            atomicAdd(&g_cnt[(int)d0.x], 1);
            atomicAdd(&g_cnt[(int)d0.y], 1);
            atomicAdd(&g_cnt[(int)d1.x], 1);
            atomicAdd(&g_cnt[(int)d1.y], 1);
        } else {
            for (int j = 0; j < 4 && base + j < ne; j++)
                atomicAdd(&g_cnt[(int)p[base + j]], 1);
        }
    } else {
        const int* p = (const int*)ei + ne;
        if (vec) {
            int4 d = __ldg((const int4*)(p + base));
            atomicAdd(&g_cnt[d.x], 1);
            atomicAdd(&g_cnt[d.y], 1);
            atomicAdd(&g_cnt[d.z], 1);
            atomicAdd(&g_cnt[d.w], 1);
        } else {
            for (int j = 0; j < 4 && base + j < ne; j++)
                atomicAdd(&g_cnt[p[base + j]], 1);
        }
    }
}

// single-block exclusive scan over g_cnt -> rowptr/cursor, plus dinv
__global__ void scan_kernel(int n) {
    __shared__ int sh[1024];
    const int t = threadIdx.x;
    const int CH = (n + 1023) / 1024;
    const int base = t * CH;

    int s = 0;
    for (int j = 0; j < CH; j++) {
        int i = base + j;
        if (i < n) s += g_cnt[i];
    }
    sh[t] = s;
    __syncthreads();
    for (int d = 1; d < 1024; d <<= 1) {
        int v = (t >= d) ? sh[t - d] : 0;
        __syncthreads();
        sh[t] += v;
        __syncthreads();
    }
    int running = sh[t] - s;
    for (int j = 0; j < CH; j++) {
        int i = base + j;
        if (i < n) {
            int c = g_cnt[i];
            g_rowptr[i] = running;
            g_cursor[i] = running;
            g_dinv[i]   = rsqrtf((float)(c + 1));
            running += c;
        }
    }
    if (t == 1023) g_rowptr[n] = sh[1023];
}

__global__ void fill_kernel(const void* ei, int ne) {
    int base = (blockIdx.x * blockDim.x + threadIdx.x) * 4;
    if (base >= ne) return;
    bool vec = (base + 3 < ne) && ((ne & 3) == 0);
    int src[4], dst[4], cnt4 = 4;
    if (g_is64) {
        const long long* ps = (const long long*)ei;
        const long long* pd = ps + ne;
        if (vec) {
            longlong2 s0 = __ldg((const longlong2*)(ps + base));
            longlong2 s1 = __ldg((const longlong2*)(ps + base + 2));
            longlong2 d0 = __ldg((const longlong2*)(pd + base));
            longlong2 d1 = __ldg((const longlong2*)(pd + base + 2));
            src[0]=(int)s0.x; src[1]=(int)s0.y; src[2]=(int)s1.x; src[3]=(int)s1.y;
            dst[0]=(int)d0.x; dst[1]=(int)d0.y; dst[2]=(int)d1.x; dst[3]=(int)d1.y;
        } else {
            cnt4 = 0;
            for (int j = 0; j < 4 && base + j < ne; j++) {
                src[cnt4] = (int)ps[base + j]; dst[cnt4] = (int)pd[base + j]; cnt4++;
            }
        }
    } else {
        const int* ps = (const int*)ei;
        const int* pd = ps + ne;
        if (vec) {
            int4 s = __ldg((const int4*)(ps + base));
            int4 d = __ldg((const int4*)(pd + base));
            src[0]=s.x; src[1]=s.y; src[2]=s.z; src[3]=s.w;
            dst[0]=d.x; dst[1]=d.y; dst[2]=d.z; dst[3]=d.w;
        } else {
            cnt4 = 0;
            for (int j = 0; j < 4 && base + j < ne; j++) {
                src[cnt4] = ps[base + j]; dst[cnt4] = pd[base + j]; cnt4++;
            }
        }
    }
    int pos[4];
    #pragma unroll
    for (int j = 0; j < 4; j++)
        if (j < cnt4) pos[j] = atomicAdd(&g_cursor[dst[j]], 1);
    #pragma unroll
    for (int j = 0; j < 4; j++)
        if (j < cnt4) g_col[pos[j]] = src[j];
}

// ---------------- GEMM (+optional row-scale):  S = (Hin @ W) [* dinv[row]] ----------------
// R13-proven structure: register-blocked 8x8, packed fp32x2 FMA, conflict-free
// split-half ws layout. W is [KDIM, NDIM] row-major.
template<int KDIM, int NDIM, int BM, int KC, int NTHREADS, bool SCALE>
__global__ void __launch_bounds__(NTHREADS)
gemm_scale_kernel(const float* __restrict__ Hin,
                  const float* __restrict__ W,
                  float* __restrict__ S,
                  int n) {
    constexpr int TM = 8, TN = 8;
    constexpr int TCOLS = NDIM / TN;
    constexpr int TROWS = BM / TM;
    static_assert(TCOLS * TROWS == NTHREADS, "thread shape");
    constexpr int KCP = KC + 4;   // row stride 144B (multiple of 16B)

    __shared__ float ws[KC][NDIM];
    __shared__ float hs[BM][KCP];

    const int tc = threadIdx.x % TCOLS;
    const int tr = threadIdx.x / TCOLS;
    const int row0 = blockIdx.x * BM;

    unsigned long long acc[TM][4];
    #pragma unroll
    for (int m = 0; m < TM; m++)
        #pragma unroll
        for (int p = 0; p < 4; p++)
            acc[m][p] = 0ULL;  // packed (0.0f, 0.0f)

    for (int kc = 0; kc < KDIM; kc += KC) {
        for (int i = threadIdx.x; i < KC * (NDIM / 4); i += NTHREADS) {
            int kk = i / (NDIM / 4), c4 = i % (NDIM / 4);
            float4 v = ((const float4*)(W + (size_t)(kc + kk) * NDIM))[c4];
            int phys = ((c4 & 1) ? (NDIM / 8) : 0) + (c4 >> 1);  // split-half permute
            ((float4*)ws[kk])[phys] = v;
        }
        for (int i = threadIdx.x; i < BM * (KC / 4); i += NTHREADS) {
            int rr = i / (KC / 4), c4 = i % (KC / 4);
            int grow = row0 + rr;
            float4 v = make_float4(0.f, 0.f, 0.f, 0.f);
            if (grow < n)
                v = ((const float4*)(Hin + (size_t)grow * KDIM + kc))[c4];
            ((float4*)hs[rr])[c4] = v;
        }
        __syncthreads();

        #pragma unroll 4
        for (int k = 0; k < KC; k++) {
            ulonglong2 w01 = *(const ulonglong2*)&ws[k][tc * 4];
            ulonglong2 w23 = *(const ulonglong2*)&ws[k][NDIM / 2 + tc * 4];
            unsigned long long ad[TM];
            #pragma unroll
            for (int m = 0; m < TM; m++) {
                float a = hs[tr * TM + m][k];
                asm("mov.b64 %0, {%1, %1};" : "=l"(ad[m]) : "f"(a));
            }
            #pragma unroll
            for (int m = 0; m < TM; m++) {
                asm("fma.rn.f32x2 %0, %1, %2, %0;" : "+l"(acc[m][0]) : "l"(ad[m]), "l"(w01.x));
                asm("fma.rn.f32x2 %0, %1, %2, %0;" : "+l"(acc[m][1]) : "l"(ad[m]), "l"(w01.y));
                asm("fma.rn.f32x2 %0, %1, %2, %0;" : "+l"(acc[m][2]) : "l"(ad[m]), "l"(w23.x));
                asm("fma.rn.f32x2 %0, %1, %2, %0;" : "+l"(acc[m][3]) : "l"(ad[m]), "l"(w23.y));
            }
        }
        __syncthreads();
    }

    #pragma unroll
    for (int m = 0; m < TM; m++) {
        int row = row0 + tr * TM + m;
        if (row < n) {
            unsigned long long r0 = acc[m][0], r1 = acc[m][1], r2 = acc[m][2], r3 = acc[m][3];
            if (SCALE) {
                float dv = g_dinv[row];
                unsigned long long dvp;
                asm("mov.b64 %0, {%1, %1};" : "=l"(dvp) : "f"(dv));
                asm("mul.rn.f32x2 %0, %0, %1;" : "+l"(r0) : "l"(dvp));
                asm("mul.rn.f32x2 %0, %0, %1;" : "+l"(r1) : "l"(dvp));
                asm("mul.rn.f32x2 %0, %0, %1;" : "+l"(r2) : "l"(dvp));
                asm("mul.rn.f32x2 %0, %0, %1;" : "+l"(r3) : "l"(dvp));
            }
            ulonglong2 o0; o0.x = r0; o0.y = r1;
            ulonglong2 o1; o1.x = r2; o1.y = r3;
            *(ulonglong2*)(S + (size_t)row * NDIM + tc * TN)     = o0;
            *(ulonglong2*)(S + (size_t)row * NDIM + tc * TN + 4) = o1;
        }
    }
}

// ---------------- CSR aggregation (+self loop +dinv +bias +relu) ----------------
// SRCSCALE: gathered rows (and the self row) are unscaled (S = H@W); multiply
// each by dinv[src] during accumulation. Identical fp ordering to pre-scaled S.
template<int NDIM, bool SRCSCALE>
__global__ void agg_kernel(const float* __restrict__ S,
                           const float* __restrict__ b,
                           float* __restrict__ H,
                           int n) {
    constexpr int G = NDIM / 4;
    constexpr int RPW = 32 / G;
    const int warpId = threadIdx.x / 32;
    const int lane = threadIdx.x % 32;
    const int g = lane % G;
    const int row = (blockIdx.x * (blockDim.x / 32) + warpId) * RPW + lane / G;
    if (row >= n) return;

    const float4* S4 = (const float4*)S;
    const float dv = g_dinv[row];

    float4 acc = __ldg(&S4[(size_t)row * G + g]);   // self loop
    if (SRCSCALE) { acc.x *= dv; acc.y *= dv; acc.z *= dv; acc.w *= dv; }

    const int start = g_rowptr[row];
    const int end   = g_rowptr[row + 1];

    int j = start;
    for (; j + 3 < end; j += 4) {
        int s0 = __ldg(&g_col[j]);
        int s1 = __ldg(&g_col[j + 1]);
        int s2 = __ldg(&g_col[j + 2]);
        int s3 = __ldg(&g_col[j + 3]);
        float4 v0 = __ldg(&S4[(size_t)s0 * G + g]);
        float4 v1 = __ldg(&S4[(size_t)s1 * G + g]);
        float4 v2 = __ldg(&S4[(size_t)s2 * G + g]);
        float4 v3 = __ldg(&S4[(size_t)s3 * G + g]);
        if (SRCSCALE) {
            float d0 = __ldg(&g_dinv[s0]), d1 = __ldg(&g_dinv[s1]);
            float d2 = __ldg(&g_dinv[s2]), d3 = __ldg(&g_dinv[s3]);
            acc.x += (d0 * v0.x + d1 * v1.x) + (d2 * v2.x + d3 * v3.x);
            acc.y += (d0 * v0.y + d1 * v1.y) + (d2 * v2.y + d3 * v3.y);
            acc.z += (d0 * v0.z + d1 * v1.z) + (d2 * v2.z + d3 * v3.z);
            acc.w += (d0 * v0.w + d1 * v1.w) + (d2 * v2.w + d3 * v3.w);
        } else {
            acc.x += (v0.x + v1.x) + (v2.x + v3.x);
            acc.y += (v0.y + v1.y) + (v2.y + v3.y);
            acc.z += (v0.z + v1.z) + (v2.z + v3.z);
            acc.w += (v0.w + v1.w) + (v2.w + v3.w);
        }
    }
    for (; j < end; j++) {
        int s0 = __ldg(&g_col[j]);
        float4 v0 = __ldg(&S4[(size_t)s0 * G + g]);
        if (SRCSCALE) {
            float d0 = __ldg(&g_dinv[s0]);
            acc.x += d0 * v0.x; acc.y += d0 * v0.y;
            acc.z += d0 * v0.z; acc.w += d0 * v0.w;
        } else {
            acc.x += v0.x; acc.y += v0.y; acc.z += v0.z; acc.w += v0.w;
        }
    }

    float4 bb = ((const float4*)b)[g];
    float4 h;
    h.x = fmaxf(dv * acc.x + bb.x, 0.f);
    h.y = fmaxf(dv * acc.y + bb.y, 0.f);
    h.z = fmaxf(dv * acc.z + bb.z, 0.f);
    h.w = fmaxf(dv * acc.w + bb.w, 0.f);
    ((float4*)(H + (size_t)row * NDIM))[g] = h;
}

// ---------------- fused layer-3 aggregation + head ----------------
__global__ void agg_final_kernel(const float* __restrict__ S,
                                 const float* __restrict__ b,
                                 const void* __restrict__ y,
                                 const float* __restrict__ proto,
                                 const float* __restrict__ Wf0,
                                 const float* __restrict__ bf0,
                                 const float* __restrict__ Wf1,
                                 const float* __restrict__ bf1,
                                 float* __restrict__ out,
                                 int n) {
    constexpr int G = 16;
    __shared__ float ps[NPROTO_C][H3_C];
    __shared__ float psq[NPROTO_C];
    __shared__ float w0[NPROTO_C][MLP_H_C];
    __shared__ float b0[MLP_H_C];
    __shared__ float w1[MLP_H_C];
    __shared__ float b1s;

    for (int i = threadIdx.x; i < NPROTO_C * H3_C; i += blockDim.x)
        ps[i / H3_C][i % H3_C] = proto[i];
    for (int i = threadIdx.x; i < NPROTO_C * MLP_H_C; i += blockDim.x)
        w0[i / MLP_H_C][i % MLP_H_C] = Wf0[i];
    if (threadIdx.x < MLP_H_C) {
        b0[threadIdx.x] = bf0[threadIdx.x];
        w1[threadIdx.x] = Wf1[threadIdx.x];
    }
    if (threadIdx.x == 0) b1s = bf1[0];
    __syncthreads();
    if (threadIdx.x < NPROTO_C) {
        float s = 0.f;
        for (int j = 0; j < H3_C; j++) s += ps[threadIdx.x][j] * ps[threadIdx.x][j];
        psq[threadIdx.x] = s;
    }
    __syncthreads();

    const int warpId = threadIdx.x / 32;
    const int lane = threadIdx.x % 32;
    const int g = lane % G;
    int row = (blockIdx.x * (blockDim.x / 32) + warpId) * 2 + lane / G;
    const bool valid = (row < n);
    if (!valid) row = n - 1;   // clamp: keep full warp for shfl

    const float4* S4 = (const float4*)S;
    float4 acc = __ldg(&S4[(size_t)row * G + g]);
    const int start = g_rowptr[row];
    const int end   = g_rowptr[row + 1];
    int j = start;
    for (; j + 3 < end; j += 4) {
        int s0 = __ldg(&g_col[j]);
        int s1 = __ldg(&g_col[j + 1]);
        int s2 = __ldg(&g_col[j + 2]);
        int s3 = __ldg(&g_col[j + 3]);
        float4 v0 = __ldg(&S4[(size_t)s0 * G + g]);
        float4 v1 = __ldg(&S4[(size_t)s1 * G + g]);
        float4 v2 = __ldg(&S4[(size_t)s2 * G + g]);
        float4 v3 = __ldg(&S4[(size_t)s3 * G + g]);
        acc.x += (v0.x + v1.x) + (v2.x + v3.x);
        acc.y += (v0.y + v1.y) + (v2.y + v3.y);
        acc.z += (v0.z + v1.z) + (v2.z + v3.z);
        acc.w += (v0.w + v1.w) + (v2.w + v3.w);
    }
    for (; j < end; j++) {
        int s0 = __ldg(&g_col[j]);
        float4 v0 = __ldg(&S4[(size_t)s0 * G + g]);
        acc.x += v0.x; acc.y += v0.y; acc.z += v0.z; acc.w += v0.w;
    }

    float dv = g_dinv[row];
    float4 bb = ((const float4*)b)[g];
    float4 h;
    h.x = fmaxf(dv * acc.x + bb.x, 0.f);
    h.y = fmaxf(dv * acc.y + bb.y, 0.f);
    h.z = fmaxf(dv * acc.z + bb.z, 0.f);
    h.w = fmaxf(dv * acc.w + bb.w, 0.f);

    float hh = h.x * h.x + h.y * h.y + h.z * h.z + h.w * h.w;
    float dot[NPROTO_C];
    #pragma unroll
    for (int p = 0; p < NPROTO_C; p++) {
        dot[p] = h.x * ps[p][4 * g + 0] + h.y * ps[p][4 * g + 1]
               + h.z * ps[p][4 * g + 2] + h.w * ps[p][4 * g + 3];
    }

    #pragma unroll
    for (int off = 8; off >= 1; off >>= 1) {
        hh += __shfl_xor_sync(0xffffffffu, hh, off);
        #pragma unroll
        for (int p = 0; p < NPROTO_C; p++)
            dot[p] += __shfl_xor_sync(0xffffffffu, dot[p], off);
    }

    float d2 = fmaxf(hh + psq[g] - 2.f * dot[g], 0.f);
    float sim = logf((d2 + 1.0f) / (d2 + 1e-4f));
    float z[MLP_H_C];
    #pragma unroll
    for (int jj = 0; jj < MLP_H_C; jj++) z[jj] = sim * w0[g][jj];
    #pragma unroll
    for (int off = 8; off >= 1; off >>= 1) {
        #pragma unroll
        for (int jj = 0; jj < MLP_H_C; jj++)
            z[jj] += __shfl_xor_sync(0xffffffffu, z[jj], off);
    }

    if (g == 0 && valid) {
        float t = b1s;
        #pragma unroll
        for (int jj = 0; jj < MLP_H_C; jj++) {
            float x = z[jj] + b0[jj];
            float gl = 0.5f * x * (1.0f + erff(x * 0.70710678118654752f));
            t += gl * w1[jj];
        }
        out[row] = 1.0f / (1.0f + expf(-t));
        if (g_is64) out[n + row] = (float)((const long long*)y)[row];
        else        out[n + row] = (float)((const int*)y)[row];
    }
}

// ---------------- launch ----------------
extern "C" void kernel_launch(void* const* d_in, const int* in_sizes, int n_in,
                              void* d_out, int out_size) {
    const float* x     = (const float*)d_in[0];
    const void*  ei    = d_in[1];
    const void*  y     = d_in[2];
    const float* W1    = (const float*)d_in[3];
    const float* b1    = (const float*)d_in[4];
    const float* W2    = (const float*)d_in[5];
    const float* b2    = (const float*)d_in[6];
    const float* W3    = (const float*)d_in[7];
    const float* b3    = (const float*)d_in[8];
    const float* proto = (const float*)d_in[9];
    const float* Wf0   = (const float*)d_in[10];
    const float* bf0   = (const float*)d_in[11];
    const float* Wf1   = (const float*)d_in[12];
    const float* bf1   = (const float*)d_in[13];
    float* out = (float*)d_out;

    const int n  = in_sizes[0] / D_IN_C;
    const int ne = in_sizes[1] / 2;

    float* S = nullptr; float* H = nullptr; int* cnt = nullptr;
    cudaGetSymbolAddress((void**)&S, g_S);
    cudaGetSymbolAddress((void**)&H, g_H);
    cudaGetSymbolAddress((void**)&cnt, g_cnt);

    // streams/events created once, on the (uncaptured) correctness call
    static cudaStream_t s_side = nullptr;
    static cudaEvent_t ev_fork = nullptr, ev_join = nullptr;
    if (s_side == nullptr) {
        cudaStreamCreateWithFlags(&s_side, cudaStreamNonBlocking);
        cudaEventCreateWithFlags(&ev_fork, cudaEventDisableTiming);
        cudaEventCreateWithFlags(&ev_join, cudaEventDisableTiming);
    }

    // ---- fork: CSR build on side stream, gemm1 (no dinv needed) on main ----
    cudaEventRecord(ev_fork, 0);
    cudaStreamWaitEvent(s_side, ev_fork, 0);

    int nt4 = (ne + 3) / 4;
    cudaMemsetAsync(cnt, 0, (size_t)n * sizeof(int), s_side);
    detect_idx_kernel<<<1, 1, 0, s_side>>>(ei, n);
    count_kernel<<<(nt4 + 255) / 256, 256, 0, s_side>>>(ei, ne);
    scan_kernel<<<1, 1024, 0, s_side>>>(n);
    fill_kernel<<<(nt4 + 255) / 256, 256, 0, s_side>>>(ei, ne);
    cudaEventRecord(ev_join, s_side);

    // gemm1: 128 -> 128, R13 config (BM=128, 256 threads), unscaled output
    gemm_scale_kernel<D_IN_C, H1_C, 128, 32, 256, false>
        <<<(n + 127) / 128, 256>>>(x, W1, S, n);

    // ---- join ----
    cudaStreamWaitEvent(0, ev_join, 0);

    // ---- layer 1 aggregation (applies dinv[src] per gather + dinv[row]) ----
    {
        int rpb = (256 / 32) * (32 / (H1_C / 4));
        agg_kernel<H1_C, true><<<(n + rpb - 1) / rpb, 256>>>(S, b1, H, n);
    }
    // ---- layer 2: 128 -> 64 ----
    {
        gemm_scale_kernel<H1_C, H2_C, 128, 32, 128, true>
            <<<(n + 127) / 128, 128>>>(H, W2, S, n);
        int rpb = (256 / 32) * (32 / (H2_C / 4));
        agg_kernel<H2_C, false><<<(n + rpb - 1) / rpb, 256>>>(S, b2, H, n);
    }
    // ---- layer 3: 64 -> 64, fused with head ----
    {
        gemm_scale_kernel<H2_C, H3_C, 128, 32, 128, true>
            <<<(n + 127) / 128, 128>>>(H, W3, S, n);
        int rpb = (256 / 32) * 2;   // 16 rows per 256-thread block
        agg_final_kernel<<<(n + rpb - 1) / rpb, 256>>>(S, b3, y, proto,
                                                       Wf0, bf0, Wf1, bf1, out, n);
    }
}